// round 11
// baseline (speedup 1.0000x reference)
#include <cuda_runtime.h>
#include <cuda_bf16.h>

#define NU      50001
#define NI      100001
#define NN      150002
#define DD      64
#define NE      2000000
#define BATCHSZ 2048
#define EPSF    1e-9f
#define GAMMAF  1e-10f
#define INIT_BLOCKS 9376   // ceil(NN*DD/4 / 256)
#define NORM_ELEMS  (2 * NN)
#define SCHUNK  4096
#define SNB     37         // ceil(NN / SCHUNK)
#define GB      18751      // ceil(NN / 8)
#define LOSSB   256        // BATCHSZ warps / 8 warps per block

// ---------------- static scratch ----------------
__device__ __align__(128) float g_total[2][(size_t)NN * DD]; // ping-pong, 76.8 MB
__device__ int   g_cnt[2 * NN];
__device__ int   g_off[2 * (NN + 1)];
__device__ int   g_rank[2 * NE];                             // edge rank within dst bucket
__device__ int   g_csrc[2 * NE];                             // CSR: src per slot
__device__ float g_ns[2 * NN];                               // 1/(den+eps)  (== norm)
__device__ float g_rs[2 * NN];                               // old_scale/(den+eps)
__device__ float g_bpr[2 * BATCHSZ];
__device__ float g_squ[INIT_BLOCKS];
__device__ float g_sqi[INIT_BLOCKS];
__device__ int   g_bsum[2 * SNB];

// ---------------------------------------------------------------------------
// 1) fused: total[0] = concat(user,item) + sumsq partials + per-node norms
// ---------------------------------------------------------------------------
__global__ __launch_bounds__(256) void init_kernel(
    const float4* __restrict__ ue, const float4* __restrict__ ie,
    const float* __restrict__ oldd, const float* __restrict__ nowd,
    const float* __restrict__ dwp, const float* __restrict__ owp)
{
    __shared__ float shu[256], shi[256];
    int i = blockIdx.x * 256 + threadIdx.x;

    // ---- norm part (first 2*NN threads chip-wide) ----
    if (i < NORM_ELEMS) {
        float dw = __ldg(dwp), ow = __ldg(owp);
        float od = __ldg(oldd + i), nd = __ldg(nowd + i);
        float den = sqrtf(fmaxf(od * dw, 0.f) + nd);
        float inv = 1.f / (den + EPSF);
        g_ns[i] = inv;
        g_rs[i] = sqrtf(fmaxf(od * ow, 0.f)) * inv;
        g_cnt[i] = 0;
    }

    // ---- concat + sumsq part ----
    const int tot4 = NN * DD / 4;
    const int nu4  = NU * DD / 4;
    float su = 0.f, si = 0.f;
    if (i < tot4) {
        float4 v;
        if (i < nu4) { v = ue[i]; su = v.x*v.x + v.y*v.y + v.z*v.z + v.w*v.w; }
        else         { v = ie[i - nu4]; si = v.x*v.x + v.y*v.y + v.z*v.z + v.w*v.w; }
        ((float4*)g_total[0])[i] = v;
    }
    shu[threadIdx.x] = su; shi[threadIdx.x] = si;
    __syncthreads();
    for (int s = 128; s; s >>= 1) {
        if (threadIdx.x < s) {
            shu[threadIdx.x] += shu[threadIdx.x + s];
            shi[threadIdx.x] += shi[threadIdx.x + s];
        }
        __syncthreads();
    }
    if (threadIdx.x == 0) { g_squ[blockIdx.x] = shu[0]; g_sqi[blockIdx.x] = shi[0]; }
}

// ---------------------------------------------------------------------------
// 2) histogram over dst, int4-vectorized; atomic return value == edge rank
// ---------------------------------------------------------------------------
__global__ __launch_bounds__(256) void hist_kernel(const int4* __restrict__ dst4) {
    int i = blockIdx.x * 256 + threadIdx.x;      // [0, 2*NE/4)
    if (i >= 2 * NE / 4) return;
    int4 d = __ldg(dst4 + i);
    int* c = g_cnt + (i >= NE / 4 ? NN : 0);
    int4 r;
    r.x = atomicAdd(c + d.x, 1);
    r.y = atomicAdd(c + d.y, 1);
    r.z = atomicAdd(c + d.z, 1);
    r.w = atomicAdd(c + d.w, 1);
    ((int4*)g_rank)[i] = r;
}

// ---------------------------------------------------------------------------
// 3a) chunk sums
// ---------------------------------------------------------------------------
__global__ __launch_bounds__(256) void reduce_kernel() {
    __shared__ int sh[256];
    int blk = blockIdx.x;              // [0, 2*SNB)
    int b   = blk >= SNB;
    int c   = blk - b * SNB;
    const int* cnt = g_cnt + b * NN;
    int s = 0;
    int base = c * SCHUNK;
    #pragma unroll
    for (int k = 0; k < SCHUNK / 256; k++) {
        int i = base + k * 256 + threadIdx.x;
        if (i < NN) s += cnt[i];
    }
    sh[threadIdx.x] = s;
    __syncthreads();
    for (int st = 128; st; st >>= 1) {
        if (threadIdx.x < st) sh[threadIdx.x] += sh[threadIdx.x + st];
        __syncthreads();
    }
    if (threadIdx.x == 0) g_bsum[blk] = sh[0];
}

// ---------------------------------------------------------------------------
// 3b) intra-chunk exclusive scan; base computed in-kernel from g_bsum
// ---------------------------------------------------------------------------
__global__ __launch_bounds__(1024) void scanc_kernel() {
    int blk = blockIdx.x;              // [0, 2*SNB)
    int b   = blk >= SNB;
    int c   = blk - b * SNB;
    int tid = threadIdx.x, lane = tid & 31, wid = tid >> 5;
    __shared__ int wsum[32];
    __shared__ int sbase;

    // warp 0 computes base = sum of g_bsum[b*SNB .. b*SNB + c)
    if (wid == 0) {
        int acc = 0;
        for (int i = lane; i < c; i += 32) acc += g_bsum[b * SNB + i];
        #pragma unroll
        for (int o = 16; o; o >>= 1) acc += __shfl_xor_sync(~0u, acc, o);
        if (lane == 0) sbase = acc;
    }

    const int* cnt = g_cnt + b * NN;
    int* off = g_off + b * (NN + 1);

    int i0 = c * SCHUNK + tid * 4;
    int v0 = (i0 + 0 < NN) ? cnt[i0 + 0] : 0;
    int v1 = (i0 + 1 < NN) ? cnt[i0 + 1] : 0;
    int v2 = (i0 + 2 < NN) ? cnt[i0 + 2] : 0;
    int v3 = (i0 + 3 < NN) ? cnt[i0 + 3] : 0;
    int ts = v0 + v1 + v2 + v3;
    int x = ts;
    #pragma unroll
    for (int o = 1; o < 32; o <<= 1) { int y = __shfl_up_sync(~0u, x, o); if (lane >= o) x += y; }
    if (lane == 31) wsum[wid] = x;
    __syncthreads();
    if (wid == 0) {
        int w = wsum[lane];
        #pragma unroll
        for (int o = 1; o < 32; o <<= 1) { int y = __shfl_up_sync(~0u, w, o); if (lane >= o) w += y; }
        wsum[lane] = w;
    }
    __syncthreads();
    int excl = sbase + (x - ts) + (wid ? wsum[wid - 1] : 0);
    if (i0 + 0 < NN) off[i0 + 0] = excl; excl += v0;
    if (i0 + 1 < NN) off[i0 + 1] = excl; excl += v1;
    if (i0 + 2 < NN) off[i0 + 2] = excl; excl += v2;
    if (i0 + 3 < NN) off[i0 + 3] = excl;
    if (tid == 0 && c == 0) off[NN] = NE;   // total edges per behavior is exact
}

// ---------------------------------------------------------------------------
// 4) CSR fill — atomic-free: pos = off[dst] + rank
// ---------------------------------------------------------------------------
__global__ __launch_bounds__(256) void fill_kernel(const int4* __restrict__ src4,
                                                   const int4* __restrict__ dst4) {
    int i = blockIdx.x * 256 + threadIdx.x;      // [0, 2*NE/4)
    if (i >= 2 * NE / 4) return;
    int b = (i >= NE / 4);
    int4 d = __ldg(dst4 + i);
    int4 s = __ldg(src4 + i);
    int4 r = __ldcs(((const int4*)g_rank) + i);
    const int* off = g_off + b * (NN + 1);
    int* csrc = g_csrc + (size_t)b * NE;
    csrc[__ldg(off + d.x) + r.x] = s.x;
    csrc[__ldg(off + d.y) + r.y] = s.y;
    csrc[__ldg(off + d.z) + r.z] = s.z;
    csrc[__ldg(off + d.w) + r.w] = s.w;
}

// ---------------------------------------------------------------------------
// device helper: BPR loss for one warp/sample
// ---------------------------------------------------------------------------
__device__ __forceinline__ void bpr_sample(const int* __restrict__ bdata,
                                           int b, int which, int w, int lane) {
    const float* emb = g_total[which];
    const int* r = bdata + (size_t)w * 6 + (size_t)b * 3;  // (BATCH, 2, 3)
    int u  = __ldg(r + 0);
    int pi = NU + __ldg(r + 1);
    int ni = NU + __ldg(r + 2);

    float2 uv = *(const float2*)(emb + (size_t)u  * DD + lane * 2);
    float2 pv = *(const float2*)(emb + (size_t)pi * DD + lane * 2);
    float2 nv = *(const float2*)(emb + (size_t)ni * DD + lane * 2);

    float s0 = uv.x * pv.x + uv.y * pv.y;
    float s1 = uv.x * nv.x + uv.y * nv.y;
    #pragma unroll
    for (int o = 16; o; o >>= 1) {
        s0 += __shfl_xor_sync(0xffffffffu, s0, o);
        s1 += __shfl_xor_sync(0xffffffffu, s1, o);
    }
    if (lane == 0) {
        float diff = s0 - s1;
        float sig  = 1.f / (1.f + expf(-diff));
        g_bpr[b * BATCHSZ + w] = -logf(GAMMAF + sig);
    }
}

// ---------------------------------------------------------------------------
// 5) fused gather + combine; streaming loads for read-once data
// ---------------------------------------------------------------------------
__global__ __launch_bounds__(256) void gathcomb_kernel(
    const float* __restrict__ ls,     // last_stage[b] : [2][NN][DD]
    const float* __restrict__ cw,     // conv_w[b] : 4 floats
    int b, int p,
    const int* __restrict__ bdata, int lb, int lwhich)
{
    int lane = threadIdx.x & 31;
    if (blockIdx.x >= GB) {
        int w = (blockIdx.x - GB) * 8 + (threadIdx.x >> 5);
        if (w < BATCHSZ && lb >= 0) bpr_sample(bdata, lb, lwhich, w, lane);
        return;
    }

    int node = blockIdx.x * 8 + (threadIdx.x >> 5);
    if (node >= NN) return;
    int half = lane >> 4;      // 0/1: which edge of the pair
    int q    = lane & 15;      // float4 slot within row

    const float* tot_in  = g_total[p];
    float*       tot_out = g_total[1 - p];
    const int*   csrc    = g_csrc + (size_t)b * NE;
    const float* nsb     = g_ns + b * NN;

    int r0  = __ldg(g_off + b * (NN + 1) + node);
    int r1  = __ldg(g_off + b * (NN + 1) + node + 1);
    int cnt = r1 - r0;

    float4 acc = make_float4(0.f, 0.f, 0.f, 0.f);
    for (int base = 0; base < cnt; base += 32) {
        int mm = min(32, cnt - base);
        int myidx = 0; float myns = 0.f;
        if (base + lane < cnt) {
            myidx = __ldcs(csrc + r0 + base + lane);    // stream CSR indices
            myns  = __ldg(nsb + myidx);
        }
        int kend = mm & ~1;
        #pragma unroll 4
        for (int k = 0; k < kend; k += 2) {
            int   s = __shfl_sync(0xffffffffu, myidx, k + half);
            float w = __shfl_sync(0xffffffffu, myns,  k + half);
            float4 v = __ldg((const float4*)(tot_in + (size_t)s * DD + q * 4));
            acc.x = fmaf(w, v.x, acc.x);
            acc.y = fmaf(w, v.y, acc.y);
            acc.z = fmaf(w, v.z, acc.z);
            acc.w = fmaf(w, v.w, acc.w);
        }
        if (mm & 1) {
            int   s = __shfl_sync(0xffffffffu, myidx, kend);
            float w = __shfl_sync(0xffffffffu, myns,  kend);
            if (half == 0) {
                float4 v = __ldg((const float4*)(tot_in + (size_t)s * DD + q * 4));
                acc.x = fmaf(w, v.x, acc.x);
                acc.y = fmaf(w, v.y, acc.y);
                acc.z = fmaf(w, v.z, acc.z);
                acc.w = fmaf(w, v.w, acc.w);
            }
        }
    }
    acc.x += __shfl_xor_sync(0xffffffffu, acc.x, 16);
    acc.y += __shfl_xor_sync(0xffffffffu, acc.y, 16);
    acc.z += __shfl_xor_sync(0xffffffffu, acc.z, 16);
    acc.w += __shfl_xor_sync(0xffffffffu, acc.w, 16);

    float inv = __ldg(g_ns + b * NN + node);
    float rs  = __ldg(g_rs + b * NN + node);
    float c00 = __ldg(cw + 0), c01 = __ldg(cw + 1);
    float c10 = __ldg(cw + 2), c11 = __ldg(cw + 3);

    size_t base4 = (size_t)node * DD + q * 4;
    float4 t  = __ldg((const float4*)(tot_in + base4));
    float4 l0 = __ldcs((const float4*)(ls + base4));                    // stream
    float4 l1 = __ldcs((const float4*)(ls + (size_t)NN * DD + base4));  // stream

    float4 m4;
    m4.x = (t.x + (c00 * l0.x * rs + c01 * t.x) + (c10 * l1.x * rs + c11 * (inv * acc.x))) * (1.f / 3.f);
    m4.y = (t.y + (c00 * l0.y * rs + c01 * t.y) + (c10 * l1.y * rs + c11 * (inv * acc.y))) * (1.f / 3.f);
    m4.z = (t.z + (c00 * l0.z * rs + c01 * t.z) + (c10 * l1.z * rs + c11 * (inv * acc.z))) * (1.f / 3.f);
    m4.w = (t.w + (c00 * l0.w * rs + c01 * t.w) + (c10 * l1.w * rs + c11 * (inv * acc.w))) * (1.f / 3.f);

    float sq = m4.x * m4.x + m4.y * m4.y + m4.z * m4.z + m4.w * m4.w;
    #pragma unroll
    for (int o = 8; o; o >>= 1) sq += __shfl_xor_sync(0xffffffffu, sq, o);  // 16-lane groups
    float rn = 1.f / fmaxf(sqrtf(sq), 1e-12f);

    if (half == 0) {
        float4 outv = make_float4(t.x + m4.x * rn, t.y + m4.y * rn,
                                  t.z + m4.z * rn, t.w + m4.w * rn);
        *(float4*)(tot_out + base4) = outv;
    }
}

// ---------------------------------------------------------------------------
// 6) standalone BPR loss (behavior 1)
// ---------------------------------------------------------------------------
__global__ __launch_bounds__(256) void loss_kernel(const int* __restrict__ bdata,
                                                   int b, int which) {
    int w = (blockIdx.x * blockDim.x + threadIdx.x) >> 5;
    if (w >= BATCHSZ) return;
    bpr_sample(bdata, b, which, w, threadIdx.x & 31);
}

// ---------------------------------------------------------------------------
// 7) final deterministic reduction -> out[0]
// ---------------------------------------------------------------------------
__global__ __launch_bounds__(1024) void final_kernel(float* __restrict__ out) {
    __shared__ float sh[1024];
    int t = threadIdx.x;

    float a = 0.f;
    for (int i = t; i < 2 * BATCHSZ; i += 1024) a += g_bpr[i];
    float su = 0.f, si = 0.f;
    for (int i = t; i < INIT_BLOCKS; i += 1024) { su += g_squ[i]; si += g_sqi[i]; }

    float res[3] = {a, su, si};
    float red[3];
    #pragma unroll
    for (int k = 0; k < 3; k++) {
        sh[t] = res[k];
        __syncthreads();
        for (int s = 512; s; s >>= 1) {
            if (t < s) sh[t] += sh[t + s];
            __syncthreads();
        }
        red[k] = sh[0];
        __syncthreads();
    }

    if (t == 0) {
        float total_loss = red[0] * (1.f / BATCHSZ);
        float emb_loss   = (sqrtf(red[1]) + sqrtf(red[2])) / (float)NI;
        out[0] = total_loss + 1e-4f * emb_loss;
    }
}

// ---------------------------------------------------------------------------
extern "C" void kernel_launch(void* const* d_in, const int* in_sizes, int n_in,
                              void* d_out, int out_size) {
    const float* ue    = (const float*)d_in[0];
    const float* ie    = (const float*)d_in[1];
    const float* nowd  = (const float*)d_in[2];
    const float* oldd  = (const float*)d_in[3];
    const float* ls    = (const float*)d_in[4];
    const float* dw    = (const float*)d_in[5];
    const float* ow    = (const float*)d_in[6];
    const float* cw    = (const float*)d_in[7];
    const int*   src   = (const int*)d_in[8];
    const int*   dst   = (const int*)d_in[9];
    const int*   bdata = (const int*)d_in[10];
    float*       out   = (float*)d_out;

    init_kernel<<<INIT_BLOCKS, 256>>>((const float4*)ue, (const float4*)ie,
                                      oldd, nowd, dw, ow);
    hist_kernel<<<(2 * NE / 4 + 255) / 256, 256>>>((const int4*)dst);
    reduce_kernel<<<2 * SNB, 256>>>();
    scanc_kernel<<<2 * SNB, 1024>>>();
    fill_kernel<<<(2 * NE / 4 + 255) / 256, 256>>>((const int4*)src, (const int4*)dst);

    // behavior 0: read buf0 -> write buf1 (no loss tail)
    gathcomb_kernel<<<GB, 256>>>(ls, cw + 0, 0, 0, bdata, -1, 0);
    // behavior 1: read buf1 -> write buf0 ; tail blocks run loss(b=0) on buf1
    gathcomb_kernel<<<GB + LOSSB, 256>>>(ls + (size_t)2 * NN * DD, cw + 4, 1, 1,
                                         bdata, 0, 1);
    loss_kernel<<<(BATCHSZ * 32 + 255) / 256, 256>>>(bdata, 1, 0);

    final_kernel<<<1, 1024>>>(out);
}

// round 12
// speedup vs baseline: 1.8907x; 1.8907x over previous
#include <cuda_runtime.h>
#include <cuda_bf16.h>

#define NU      50001
#define NI      100001
#define NN      150002
#define DD      64
#define NE      2000000
#define BATCHSZ 2048
#define EPSF    1e-9f
#define GAMMAF  1e-10f
#define INIT_BLOCKS 9376   // ceil(NN*DD/4 / 256)
#define NORM_ELEMS  (2 * NN)
#define SCHUNK  4096
#define SNB     37         // ceil(NN / SCHUNK)
#define GB      18751      // ceil(NN / 8)

// ---------------- static scratch ----------------
__device__ __align__(128) float g_total[2][(size_t)NN * DD]; // ping-pong, 76.8 MB
__device__ int   g_cnt[2 * NN];
__device__ int   g_off[2 * (NN + 1)];
__device__ int   g_cur[2 * NN];
__device__ int   g_csrc[2 * NE];                             // CSR: src per slot
__device__ float g_ns[2 * NN];                               // 1/(den+eps)
__device__ float g_rs[2 * NN];                               // old_scale/(den+eps)
__device__ float g_bemb[(size_t)3 * BATCHSZ * DD];           // b=1 batch embeddings
__device__ float g_bpr[2 * BATCHSZ];
__device__ float g_squ[INIT_BLOCKS];
__device__ float g_sqi[INIT_BLOCKS];
__device__ int   g_bsum[2 * SNB];
__device__ int   g_bbase[2 * SNB];

// ---------------------------------------------------------------------------
// 1) fused: total[0] = concat(user,item) + sumsq partials + per-node norms
// ---------------------------------------------------------------------------
__global__ __launch_bounds__(256) void init_kernel(
    const float4* __restrict__ ue, const float4* __restrict__ ie,
    const float* __restrict__ oldd, const float* __restrict__ nowd,
    const float* __restrict__ dwp, const float* __restrict__ owp)
{
    __shared__ float shu[256], shi[256];
    int i = blockIdx.x * 256 + threadIdx.x;

    if (i < NORM_ELEMS) {
        float dw = __ldg(dwp), ow = __ldg(owp);
        float od = __ldg(oldd + i), nd = __ldg(nowd + i);
        float den = sqrtf(fmaxf(od * dw, 0.f) + nd);
        float inv = 1.f / (den + EPSF);
        g_ns[i] = inv;
        g_rs[i] = sqrtf(fmaxf(od * ow, 0.f)) * inv;
        g_cnt[i] = 0;
    }

    const int tot4 = NN * DD / 4;
    const int nu4  = NU * DD / 4;
    float su = 0.f, si = 0.f;
    if (i < tot4) {
        float4 v;
        if (i < nu4) { v = ue[i]; su = v.x*v.x + v.y*v.y + v.z*v.z + v.w*v.w; }
        else         { v = ie[i - nu4]; si = v.x*v.x + v.y*v.y + v.z*v.z + v.w*v.w; }
        ((float4*)g_total[0])[i] = v;
    }
    shu[threadIdx.x] = su; shi[threadIdx.x] = si;
    __syncthreads();
    for (int s = 128; s; s >>= 1) {
        if (threadIdx.x < s) {
            shu[threadIdx.x] += shu[threadIdx.x + s];
            shi[threadIdx.x] += shi[threadIdx.x + s];
        }
        __syncthreads();
    }
    if (threadIdx.x == 0) { g_squ[blockIdx.x] = shu[0]; g_sqi[blockIdx.x] = shi[0]; }
}

// ---------------------------------------------------------------------------
// 2) histogram over dst, int4-vectorized (return value unused -> REDG)
// ---------------------------------------------------------------------------
__global__ __launch_bounds__(256) void hist_kernel(const int4* __restrict__ dst4) {
    int i = blockIdx.x * 256 + threadIdx.x;      // [0, 2*NE/4)
    if (i >= 2 * NE / 4) return;
    int4 d = __ldg(dst4 + i);
    int* c = g_cnt + (i >= NE / 4 ? NN : 0);
    atomicAdd(c + d.x, 1);
    atomicAdd(c + d.y, 1);
    atomicAdd(c + d.z, 1);
    atomicAdd(c + d.w, 1);
}

// ---------------------------------------------------------------------------
// 3a) chunk sums
// ---------------------------------------------------------------------------
__global__ __launch_bounds__(256) void reduce_kernel() {
    __shared__ int sh[256];
    int blk = blockIdx.x;              // [0, 2*SNB)
    int b   = blk >= SNB;
    int c   = blk - b * SNB;
    const int* cnt = g_cnt + b * NN;
    int s = 0;
    int base = c * SCHUNK;
    #pragma unroll
    for (int k = 0; k < SCHUNK / 256; k++) {
        int i = base + k * 256 + threadIdx.x;
        if (i < NN) s += cnt[i];
    }
    sh[threadIdx.x] = s;
    __syncthreads();
    for (int st = 128; st; st >>= 1) {
        if (threadIdx.x < st) sh[threadIdx.x] += sh[threadIdx.x + st];
        __syncthreads();
    }
    if (threadIdx.x == 0) g_bsum[blk] = sh[0];
}

// ---------------------------------------------------------------------------
// 3b) scan the SNB partials per behavior
// ---------------------------------------------------------------------------
__global__ void scanb_kernel() {
    int b = threadIdx.x;
    if (b < 2) {
        int run = 0;
        for (int i = 0; i < SNB; i++) {
            g_bbase[b * SNB + i] = run;
            run += g_bsum[b * SNB + i];
        }
        g_off[b * (NN + 1) + NN] = run;   // == NE
    }
}

// ---------------------------------------------------------------------------
// 3c) intra-chunk exclusive scan + base -> off, cur
// ---------------------------------------------------------------------------
__global__ __launch_bounds__(1024) void scanc_kernel() {
    int blk = blockIdx.x;              // [0, 2*SNB)
    int b   = blk >= SNB;
    int c   = blk - b * SNB;
    int tid = threadIdx.x, lane = tid & 31, wid = tid >> 5;
    __shared__ int wsum[32];

    const int* cnt = g_cnt + b * NN;
    int* off = g_off + b * (NN + 1);
    int* cur = g_cur + b * NN;

    int i0 = c * SCHUNK + tid * 4;
    int v0 = (i0 + 0 < NN) ? cnt[i0 + 0] : 0;
    int v1 = (i0 + 1 < NN) ? cnt[i0 + 1] : 0;
    int v2 = (i0 + 2 < NN) ? cnt[i0 + 2] : 0;
    int v3 = (i0 + 3 < NN) ? cnt[i0 + 3] : 0;
    int ts = v0 + v1 + v2 + v3;
    int x = ts;
    #pragma unroll
    for (int o = 1; o < 32; o <<= 1) { int y = __shfl_up_sync(~0u, x, o); if (lane >= o) x += y; }
    if (lane == 31) wsum[wid] = x;
    __syncthreads();
    if (wid == 0) {
        int w = wsum[lane];
        #pragma unroll
        for (int o = 1; o < 32; o <<= 1) { int y = __shfl_up_sync(~0u, w, o); if (lane >= o) w += y; }
        wsum[lane] = w;
    }
    __syncthreads();
    int excl = g_bbase[blk] + (x - ts) + (wid ? wsum[wid - 1] : 0);
    if (i0 + 0 < NN) { off[i0 + 0] = excl; cur[i0 + 0] = excl; } excl += v0;
    if (i0 + 1 < NN) { off[i0 + 1] = excl; cur[i0 + 1] = excl; } excl += v1;
    if (i0 + 2 < NN) { off[i0 + 2] = excl; cur[i0 + 2] = excl; } excl += v2;
    if (i0 + 3 < NN) { off[i0 + 3] = excl; cur[i0 + 3] = excl; }
}

// ---------------------------------------------------------------------------
// 4) CSR fill, int4-vectorized
// ---------------------------------------------------------------------------
__global__ __launch_bounds__(256) void fill_kernel(const int4* __restrict__ src4,
                                                   const int4* __restrict__ dst4) {
    int i = blockIdx.x * 256 + threadIdx.x;      // [0, 2*NE/4)
    if (i >= 2 * NE / 4) return;
    int b = (i >= NE / 4);
    int4 d = __ldg(dst4 + i);
    int4 s = __ldg(src4 + i);
    int* cur = g_cur + b * NN;
    int* csrc = g_csrc + (size_t)b * NE;
    csrc[atomicAdd(cur + d.x, 1)] = s.x;
    csrc[atomicAdd(cur + d.y, 1)] = s.y;
    csrc[atomicAdd(cur + d.z, 1)] = s.z;
    csrc[atomicAdd(cur + d.w, 1)] = s.w;
}

// ---------------------------------------------------------------------------
// device helper: CSR row gather (warp-collective, 2 edges/iter, float4 lanes)
// ---------------------------------------------------------------------------
__device__ __forceinline__ float4 csr_gather(const float* __restrict__ tot_in,
                                             const int* __restrict__ csrc,
                                             const float* __restrict__ nsb,
                                             int r0, int cnt,
                                             int lane, int half, int q) {
    float4 acc = make_float4(0.f, 0.f, 0.f, 0.f);
    for (int base = 0; base < cnt; base += 32) {
        int mm = min(32, cnt - base);
        int myidx = 0; float myns = 0.f;
        if (base + lane < cnt) {
            myidx = __ldg(csrc + r0 + base + lane);
            myns  = __ldg(nsb + myidx);
        }
        int kend = mm & ~1;
        #pragma unroll 4
        for (int k = 0; k < kend; k += 2) {
            int   s = __shfl_sync(0xffffffffu, myidx, k + half);
            float w = __shfl_sync(0xffffffffu, myns,  k + half);
            float4 v = __ldg((const float4*)(tot_in + (size_t)s * DD + q * 4));
            acc.x = fmaf(w, v.x, acc.x);
            acc.y = fmaf(w, v.y, acc.y);
            acc.z = fmaf(w, v.z, acc.z);
            acc.w = fmaf(w, v.w, acc.w);
        }
        if (mm & 1) {
            int   s = __shfl_sync(0xffffffffu, myidx, kend);
            float w = __shfl_sync(0xffffffffu, myns,  kend);
            if (half == 0) {
                float4 v = __ldg((const float4*)(tot_in + (size_t)s * DD + q * 4));
                acc.x = fmaf(w, v.x, acc.x);
                acc.y = fmaf(w, v.y, acc.y);
                acc.z = fmaf(w, v.z, acc.z);
                acc.w = fmaf(w, v.w, acc.w);
            }
        }
    }
    acc.x += __shfl_xor_sync(0xffffffffu, acc.x, 16);
    acc.y += __shfl_xor_sync(0xffffffffu, acc.y, 16);
    acc.z += __shfl_xor_sync(0xffffffffu, acc.z, 16);
    acc.w += __shfl_xor_sync(0xffffffffu, acc.w, 16);
    return acc;
}

// device helper: combine + row-normalize + residual; returns output float4
__device__ __forceinline__ float4 combine_row(float4 t, float4 l0, float4 l1, float4 acc,
                                              float inv, float rs,
                                              const float* __restrict__ cw) {
    float c00 = __ldg(cw + 0), c01 = __ldg(cw + 1);
    float c10 = __ldg(cw + 2), c11 = __ldg(cw + 3);
    float4 m4;
    m4.x = (t.x + (c00 * l0.x * rs + c01 * t.x) + (c10 * l1.x * rs + c11 * (inv * acc.x))) * (1.f / 3.f);
    m4.y = (t.y + (c00 * l0.y * rs + c01 * t.y) + (c10 * l1.y * rs + c11 * (inv * acc.y))) * (1.f / 3.f);
    m4.z = (t.z + (c00 * l0.z * rs + c01 * t.z) + (c10 * l1.z * rs + c11 * (inv * acc.z))) * (1.f / 3.f);
    m4.w = (t.w + (c00 * l0.w * rs + c01 * t.w) + (c10 * l1.w * rs + c11 * (inv * acc.w))) * (1.f / 3.f);
    float sq = m4.x * m4.x + m4.y * m4.y + m4.z * m4.z + m4.w * m4.w;
    #pragma unroll
    for (int o = 8; o; o >>= 1) sq += __shfl_xor_sync(0xffffffffu, sq, o);  // 16-lane groups
    float rn = 1.f / fmaxf(sqrtf(sq), 1e-12f);
    return make_float4(t.x + m4.x * rn, t.y + m4.y * rn,
                       t.z + m4.z * rn, t.w + m4.w * rn);
}

// ---------------------------------------------------------------------------
// 5) full-graph fused gather + combine, behavior 0: buf0 -> buf1
// ---------------------------------------------------------------------------
__global__ __launch_bounds__(256) void gathcomb_kernel(const float* __restrict__ ls,
                                                       const float* __restrict__ cw) {
    int node = blockIdx.x * 8 + (threadIdx.x >> 5);
    if (node >= NN) return;
    int lane = threadIdx.x & 31;
    int half = lane >> 4;
    int q    = lane & 15;

    const float* tot_in  = g_total[0];
    float*       tot_out = g_total[1];

    int r0  = __ldg(g_off + node);
    int r1  = __ldg(g_off + node + 1);

    float4 acc = csr_gather(tot_in, g_csrc, g_ns, r0, r1 - r0, lane, half, q);

    float inv = __ldg(g_ns + node);
    float rs  = __ldg(g_rs + node);

    size_t base4 = (size_t)node * DD + q * 4;
    float4 t  = __ldg((const float4*)(tot_in + base4));
    float4 l0 = __ldg((const float4*)(ls + base4));
    float4 l1 = __ldg((const float4*)(ls + (size_t)NN * DD + base4));

    float4 outv = combine_row(t, l0, l1, acc, inv, rs, cw);
    if (half == 0) *(float4*)(tot_out + base4) = outv;
}

// ---------------------------------------------------------------------------
// 6) behavior-1 gather+combine RESTRICTED to batch nodes.
//    One warp per (sample, role); reads buf1; writes g_bemb[sample*3+role].
// ---------------------------------------------------------------------------
__global__ __launch_bounds__(256) void batch_gath_kernel(const float* __restrict__ ls1,
                                                         const float* __restrict__ cw1,
                                                         const int* __restrict__ bdata) {
    int gw = blockIdx.x * 8 + (threadIdx.x >> 5);   // [0, 3*BATCHSZ)
    if (gw >= 3 * BATCHSZ) return;
    int w = gw / 3, role = gw - w * 3;
    int lane = threadIdx.x & 31;
    int half = lane >> 4;
    int q    = lane & 15;

    const int* row = bdata + (size_t)w * 6 + 3;     // behavior-1 triple
    int node = (role == 0) ? __ldg(row) : NU + __ldg(row + role);

    const float* tot_in = g_total[1];
    const int*   csrc   = g_csrc + (size_t)NE;
    const float* nsb    = g_ns + NN;

    int r0 = __ldg(g_off + (NN + 1) + node);
    int r1 = __ldg(g_off + (NN + 1) + node + 1);

    float4 acc = csr_gather(tot_in, csrc, nsb, r0, r1 - r0, lane, half, q);

    float inv = __ldg(g_ns + NN + node);
    float rs  = __ldg(g_rs + NN + node);

    size_t base4 = (size_t)node * DD + q * 4;
    float4 t  = __ldg((const float4*)(tot_in + base4));
    float4 l0 = __ldg((const float4*)(ls1 + base4));
    float4 l1 = __ldg((const float4*)(ls1 + (size_t)NN * DD + base4));

    float4 outv = combine_row(t, l0, l1, acc, inv, rs, cw1);
    if (half == 0)
        *(float4*)(g_bemb + (size_t)gw * DD + q * 4) = outv;
}

// ---------------------------------------------------------------------------
// 7) BPR loss for both behaviors: b=0 from buf1, b=1 from g_bemb
// ---------------------------------------------------------------------------
__global__ __launch_bounds__(256) void lossall_kernel(const int* __restrict__ bdata) {
    int W = blockIdx.x * 8 + (threadIdx.x >> 5);    // [0, 2*BATCHSZ)
    if (W >= 2 * BATCHSZ) return;
    int b = W >= BATCHSZ;
    int w = W - b * BATCHSZ;
    int lane = threadIdx.x & 31;

    float2 uv, pv, nv;
    if (b == 0) {
        const float* emb = g_total[1];
        const int* r = bdata + (size_t)w * 6;
        int u  = __ldg(r + 0);
        int pi = NU + __ldg(r + 1);
        int ni = NU + __ldg(r + 2);
        uv = *(const float2*)(emb + (size_t)u  * DD + lane * 2);
        pv = *(const float2*)(emb + (size_t)pi * DD + lane * 2);
        nv = *(const float2*)(emb + (size_t)ni * DD + lane * 2);
    } else {
        const float* e = g_bemb + (size_t)w * 3 * DD;
        uv = *(const float2*)(e + lane * 2);
        pv = *(const float2*)(e + DD + lane * 2);
        nv = *(const float2*)(e + 2 * DD + lane * 2);
    }

    float s0 = uv.x * pv.x + uv.y * pv.y;
    float s1 = uv.x * nv.x + uv.y * nv.y;
    #pragma unroll
    for (int o = 16; o; o >>= 1) {
        s0 += __shfl_xor_sync(0xffffffffu, s0, o);
        s1 += __shfl_xor_sync(0xffffffffu, s1, o);
    }
    if (lane == 0) {
        float diff = s0 - s1;
        float sig  = 1.f / (1.f + expf(-diff));
        g_bpr[b * BATCHSZ + w] = -logf(GAMMAF + sig);
    }
}

// ---------------------------------------------------------------------------
// 8) final deterministic reduction -> out[0]
// ---------------------------------------------------------------------------
__global__ __launch_bounds__(1024) void final_kernel(float* __restrict__ out) {
    __shared__ float sh[1024];
    int t = threadIdx.x;

    float a = 0.f;
    for (int i = t; i < 2 * BATCHSZ; i += 1024) a += g_bpr[i];
    float su = 0.f, si = 0.f;
    for (int i = t; i < INIT_BLOCKS; i += 1024) { su += g_squ[i]; si += g_sqi[i]; }

    float res[3] = {a, su, si};
    float red[3];
    #pragma unroll
    for (int k = 0; k < 3; k++) {
        sh[t] = res[k];
        __syncthreads();
        for (int s = 512; s; s >>= 1) {
            if (t < s) sh[t] += sh[t + s];
            __syncthreads();
        }
        red[k] = sh[0];
        __syncthreads();
    }

    if (t == 0) {
        float total_loss = red[0] * (1.f / BATCHSZ);
        float emb_loss   = (sqrtf(red[1]) + sqrtf(red[2])) / (float)NI;
        out[0] = total_loss + 1e-4f * emb_loss;
    }
}

// ---------------------------------------------------------------------------
extern "C" void kernel_launch(void* const* d_in, const int* in_sizes, int n_in,
                              void* d_out, int out_size) {
    const float* ue    = (const float*)d_in[0];
    const float* ie    = (const float*)d_in[1];
    const float* nowd  = (const float*)d_in[2];
    const float* oldd  = (const float*)d_in[3];
    const float* ls    = (const float*)d_in[4];
    const float* dw    = (const float*)d_in[5];
    const float* ow    = (const float*)d_in[6];
    const float* cw    = (const float*)d_in[7];
    const int*   src   = (const int*)d_in[8];
    const int*   dst   = (const int*)d_in[9];
    const int*   bdata = (const int*)d_in[10];
    float*       out   = (float*)d_out;

    init_kernel<<<INIT_BLOCKS, 256>>>((const float4*)ue, (const float4*)ie,
                                      oldd, nowd, dw, ow);
    hist_kernel<<<(2 * NE / 4 + 255) / 256, 256>>>((const int4*)dst);
    reduce_kernel<<<2 * SNB, 256>>>();
    scanb_kernel<<<1, 32>>>();
    scanc_kernel<<<2 * SNB, 1024>>>();
    fill_kernel<<<(2 * NE / 4 + 255) / 256, 256>>>((const int4*)src, (const int4*)dst);

    // behavior 0: full graph, buf0 -> buf1
    gathcomb_kernel<<<GB, 256>>>(ls, cw);
    // behavior 1: batch-restricted, buf1 -> g_bemb (6144 warps)
    batch_gath_kernel<<<3 * BATCHSZ / 8, 256>>>(ls + (size_t)2 * NN * DD, cw + 4, bdata);
    // both losses
    lossall_kernel<<<2 * BATCHSZ / 8, 256>>>(bdata);

    final_kernel<<<1, 1024>>>(out);
}

// round 16
// speedup vs baseline: 2.3225x; 1.2284x over previous
#include <cuda_runtime.h>
#include <cuda_bf16.h>

#define NU      50001
#define NI      100001
#define NN      150002
#define DD      64
#define NE      2000000
#define BATCHSZ 2048
#define EPSF    1e-9f
#define GAMMAF  1e-10f
#define INIT_BLOCKS 9376   // ceil(NN*DD/4 / 256)
#define NORM_ELEMS  (2 * NN)
#define SCHUNK  4096
#define SNB     37         // ceil(NN / SCHUNK)
#define GB      18751      // ceil(NN / 8)

// ---------------- static scratch ----------------
__device__ __align__(128) float g_total[2][(size_t)NN * DD]; // ping-pong, 76.8 MB
__device__ int   g_cnt[2 * NN];
__device__ int   g_off[2 * (NN + 1)];
__device__ int   g_cur[2 * NN];
__device__ int   g_csrc[2 * NE];                             // CSR: src per slot
__device__ float g_ns[2 * NN];                               // 1/(den+eps)
__device__ float g_rs[2 * NN];                               // old_scale/(den+eps)
__device__ float g_bemb[(size_t)3 * BATCHSZ * DD];           // b=1 batch embeddings
__device__ float g_bpr[2 * BATCHSZ];
__device__ float g_squ[INIT_BLOCKS];
__device__ float g_sqi[INIT_BLOCKS];
__device__ int   g_bsum[2 * SNB];
__device__ int   g_bbase[2 * SNB];
__device__ int   g_fb1[NN];                                  // b1 batch-node flag
__device__ int   g_fneed[NN];                                // node needs buf1 value

// ---------------------------------------------------------------------------
// 1) fused: total[0] = concat(user,item) + sumsq partials + per-node norms
//    + clear counters and flags
// ---------------------------------------------------------------------------
__global__ __launch_bounds__(256) void init_kernel(
    const float4* __restrict__ ue, const float4* __restrict__ ie,
    const float* __restrict__ oldd, const float* __restrict__ nowd,
    const float* __restrict__ dwp, const float* __restrict__ owp)
{
    __shared__ float shu[256], shi[256];
    int i = blockIdx.x * 256 + threadIdx.x;

    if (i < NORM_ELEMS) {
        float dw = __ldg(dwp), ow = __ldg(owp);
        float od = __ldg(oldd + i), nd = __ldg(nowd + i);
        float den = sqrtf(fmaxf(od * dw, 0.f) + nd);
        float inv = 1.f / (den + EPSF);
        g_ns[i] = inv;
        g_rs[i] = sqrtf(fmaxf(od * ow, 0.f)) * inv;
        g_cnt[i] = 0;
    }
    if (i < NN) { g_fb1[i] = 0; g_fneed[i] = 0; }

    const int tot4 = NN * DD / 4;
    const int nu4  = NU * DD / 4;
    float su = 0.f, si = 0.f;
    if (i < tot4) {
        float4 v;
        if (i < nu4) { v = ue[i]; su = v.x*v.x + v.y*v.y + v.z*v.z + v.w*v.w; }
        else         { v = ie[i - nu4]; si = v.x*v.x + v.y*v.y + v.z*v.z + v.w*v.w; }
        ((float4*)g_total[0])[i] = v;
    }
    shu[threadIdx.x] = su; shi[threadIdx.x] = si;
    __syncthreads();
    for (int s = 128; s; s >>= 1) {
        if (threadIdx.x < s) {
            shu[threadIdx.x] += shu[threadIdx.x + s];
            shi[threadIdx.x] += shi[threadIdx.x + s];
        }
        __syncthreads();
    }
    if (threadIdx.x == 0) { g_squ[blockIdx.x] = shu[0]; g_sqi[blockIdx.x] = shi[0]; }
}

// ---------------------------------------------------------------------------
// 2) mark batch nodes: fb1 for b1 triples (CSR filter), fneed for both triples
// ---------------------------------------------------------------------------
__global__ __launch_bounds__(256) void bmark_kernel(const int* __restrict__ bdata) {
    int w = blockIdx.x * 256 + threadIdx.x;
    if (w >= BATCHSZ) return;
    const int* r = bdata + (size_t)w * 6;
    int u0 = __ldg(r + 0), p0 = NU + __ldg(r + 1), n0 = NU + __ldg(r + 2);
    int u1 = __ldg(r + 3), p1 = NU + __ldg(r + 4), n1 = NU + __ldg(r + 5);
    g_fneed[u0] = 1; g_fneed[p0] = 1; g_fneed[n0] = 1;
    g_fneed[u1] = 1; g_fneed[p1] = 1; g_fneed[n1] = 1;
    g_fb1[u1] = 1;   g_fb1[p1] = 1;   g_fb1[n1] = 1;
}

// ---------------------------------------------------------------------------
// 3) histogram over dst; b1 edges only counted if dst is a b1 batch node
// ---------------------------------------------------------------------------
__global__ __launch_bounds__(256) void hist_kernel(const int4* __restrict__ dst4) {
    int i = blockIdx.x * 256 + threadIdx.x;      // [0, 2*NE/4)
    if (i >= 2 * NE / 4) return;
    int4 d = __ldg(dst4 + i);
    if (i < NE / 4) {
        int* c = g_cnt;
        atomicAdd(c + d.x, 1);
        atomicAdd(c + d.y, 1);
        atomicAdd(c + d.z, 1);
        atomicAdd(c + d.w, 1);
    } else {
        int* c = g_cnt + NN;
        if (__ldg(g_fb1 + d.x)) atomicAdd(c + d.x, 1);
        if (__ldg(g_fb1 + d.y)) atomicAdd(c + d.y, 1);
        if (__ldg(g_fb1 + d.z)) atomicAdd(c + d.z, 1);
        if (__ldg(g_fb1 + d.w)) atomicAdd(c + d.w, 1);
    }
}

// ---------------------------------------------------------------------------
// 4a) chunk sums
// ---------------------------------------------------------------------------
__global__ __launch_bounds__(256) void reduce_kernel() {
    __shared__ int sh[256];
    int blk = blockIdx.x;              // [0, 2*SNB)
    int b   = blk >= SNB;
    int c   = blk - b * SNB;
    const int* cnt = g_cnt + b * NN;
    int s = 0;
    int base = c * SCHUNK;
    #pragma unroll
    for (int k = 0; k < SCHUNK / 256; k++) {
        int i = base + k * 256 + threadIdx.x;
        if (i < NN) s += cnt[i];
    }
    sh[threadIdx.x] = s;
    __syncthreads();
    for (int st = 128; st; st >>= 1) {
        if (threadIdx.x < st) sh[threadIdx.x] += sh[threadIdx.x + st];
        __syncthreads();
    }
    if (threadIdx.x == 0) g_bsum[blk] = sh[0];
}

// ---------------------------------------------------------------------------
// 4b) scan the SNB partials per behavior
// ---------------------------------------------------------------------------
__global__ void scanb_kernel() {
    int b = threadIdx.x;
    if (b < 2) {
        int run = 0;
        for (int i = 0; i < SNB; i++) {
            g_bbase[b * SNB + i] = run;
            run += g_bsum[b * SNB + i];
        }
        g_off[b * (NN + 1) + NN] = run;
    }
}

// ---------------------------------------------------------------------------
// 4c) intra-chunk exclusive scan + base -> off, cur
// ---------------------------------------------------------------------------
__global__ __launch_bounds__(1024) void scanc_kernel() {
    int blk = blockIdx.x;              // [0, 2*SNB)
    int b   = blk >= SNB;
    int c   = blk - b * SNB;
    int tid = threadIdx.x, lane = tid & 31, wid = tid >> 5;
    __shared__ int wsum[32];

    const int* cnt = g_cnt + b * NN;
    int* off = g_off + b * (NN + 1);
    int* cur = g_cur + b * NN;

    int i0 = c * SCHUNK + tid * 4;
    int v0 = (i0 + 0 < NN) ? cnt[i0 + 0] : 0;
    int v1 = (i0 + 1 < NN) ? cnt[i0 + 1] : 0;
    int v2 = (i0 + 2 < NN) ? cnt[i0 + 2] : 0;
    int v3 = (i0 + 3 < NN) ? cnt[i0 + 3] : 0;
    int ts = v0 + v1 + v2 + v3;
    int x = ts;
    #pragma unroll
    for (int o = 1; o < 32; o <<= 1) { int y = __shfl_up_sync(~0u, x, o); if (lane >= o) x += y; }
    if (lane == 31) wsum[wid] = x;
    __syncthreads();
    if (wid == 0) {
        int w = wsum[lane];
        #pragma unroll
        for (int o = 1; o < 32; o <<= 1) { int y = __shfl_up_sync(~0u, w, o); if (lane >= o) w += y; }
        wsum[lane] = w;
    }
    __syncthreads();
    int excl = g_bbase[blk] + (x - ts) + (wid ? wsum[wid - 1] : 0);
    if (i0 + 0 < NN) { off[i0 + 0] = excl; cur[i0 + 0] = excl; } excl += v0;
    if (i0 + 1 < NN) { off[i0 + 1] = excl; cur[i0 + 1] = excl; } excl += v1;
    if (i0 + 2 < NN) { off[i0 + 2] = excl; cur[i0 + 2] = excl; } excl += v2;
    if (i0 + 3 < NN) { off[i0 + 3] = excl; cur[i0 + 3] = excl; }
}

// ---------------------------------------------------------------------------
// 5) CSR fill; b1 edges filtered by fb1[dst]
// ---------------------------------------------------------------------------
__global__ __launch_bounds__(256) void fill_kernel(const int4* __restrict__ src4,
                                                   const int4* __restrict__ dst4) {
    int i = blockIdx.x * 256 + threadIdx.x;      // [0, 2*NE/4)
    if (i >= 2 * NE / 4) return;
    int4 d = __ldg(dst4 + i);
    int4 s = __ldg(src4 + i);
    if (i < NE / 4) {
        int* cur = g_cur;
        int* csrc = g_csrc;
        csrc[atomicAdd(cur + d.x, 1)] = s.x;
        csrc[atomicAdd(cur + d.y, 1)] = s.y;
        csrc[atomicAdd(cur + d.z, 1)] = s.z;
        csrc[atomicAdd(cur + d.w, 1)] = s.w;
    } else {
        int* cur = g_cur + NN;
        int* csrc = g_csrc + (size_t)NE;
        if (__ldg(g_fb1 + d.x)) csrc[atomicAdd(cur + d.x, 1)] = s.x;
        if (__ldg(g_fb1 + d.y)) csrc[atomicAdd(cur + d.y, 1)] = s.y;
        if (__ldg(g_fb1 + d.z)) csrc[atomicAdd(cur + d.z, 1)] = s.z;
        if (__ldg(g_fb1 + d.w)) csrc[atomicAdd(cur + d.w, 1)] = s.w;
    }
}

// ---------------------------------------------------------------------------
// 6) frontier mark: sources of b1-batch rows need buf1
// ---------------------------------------------------------------------------
__global__ __launch_bounds__(256) void smark_kernel(const int* __restrict__ bdata) {
    int gw = blockIdx.x * 8 + (threadIdx.x >> 5);   // [0, 3*BATCHSZ)
    if (gw >= 3 * BATCHSZ) return;
    int w = gw / 3, role = gw - w * 3;
    int lane = threadIdx.x & 31;
    const int* row = bdata + (size_t)w * 6 + 3;
    int node = (role == 0) ? __ldg(row) : NU + __ldg(row + role);
    int r0 = __ldg(g_off + (NN + 1) + node);
    int r1 = __ldg(g_off + (NN + 1) + node + 1);
    const int* csrc = g_csrc + (size_t)NE;
    for (int i = r0 + lane; i < r1; i += 32)
        g_fneed[__ldg(csrc + i)] = 1;
}

// ---------------------------------------------------------------------------
// device helper: CSR row gather (warp-collective, 2 edges/iter, float4 lanes)
// ---------------------------------------------------------------------------
__device__ __forceinline__ float4 csr_gather(const float* __restrict__ tot_in,
                                             const int* __restrict__ csrc,
                                             const float* __restrict__ nsb,
                                             int r0, int cnt,
                                             int lane, int half, int q) {
    float4 acc = make_float4(0.f, 0.f, 0.f, 0.f);
    for (int base = 0; base < cnt; base += 32) {
        int mm = min(32, cnt - base);
        int myidx = 0; float myns = 0.f;
        if (base + lane < cnt) {
            myidx = __ldg(csrc + r0 + base + lane);
            myns  = __ldg(nsb + myidx);
        }
        int kend = mm & ~1;
        #pragma unroll 4
        for (int k = 0; k < kend; k += 2) {
            int   s = __shfl_sync(0xffffffffu, myidx, k + half);
            float w = __shfl_sync(0xffffffffu, myns,  k + half);
            float4 v = __ldg((const float4*)(tot_in + (size_t)s * DD + q * 4));
            acc.x = fmaf(w, v.x, acc.x);
            acc.y = fmaf(w, v.y, acc.y);
            acc.z = fmaf(w, v.z, acc.z);
            acc.w = fmaf(w, v.w, acc.w);
        }
        if (mm & 1) {
            int   s = __shfl_sync(0xffffffffu, myidx, kend);
            float w = __shfl_sync(0xffffffffu, myns,  kend);
            if (half == 0) {
                float4 v = __ldg((const float4*)(tot_in + (size_t)s * DD + q * 4));
                acc.x = fmaf(w, v.x, acc.x);
                acc.y = fmaf(w, v.y, acc.y);
                acc.z = fmaf(w, v.z, acc.z);
                acc.w = fmaf(w, v.w, acc.w);
            }
        }
    }
    acc.x += __shfl_xor_sync(0xffffffffu, acc.x, 16);
    acc.y += __shfl_xor_sync(0xffffffffu, acc.y, 16);
    acc.z += __shfl_xor_sync(0xffffffffu, acc.z, 16);
    acc.w += __shfl_xor_sync(0xffffffffu, acc.w, 16);
    return acc;
}

// device helper: combine + row-normalize + residual; returns output float4
__device__ __forceinline__ float4 combine_row(float4 t, float4 l0, float4 l1, float4 acc,
                                              float inv, float rs,
                                              const float* __restrict__ cw) {
    float c00 = __ldg(cw + 0), c01 = __ldg(cw + 1);
    float c10 = __ldg(cw + 2), c11 = __ldg(cw + 3);
    float4 m4;
    m4.x = (t.x + (c00 * l0.x * rs + c01 * t.x) + (c10 * l1.x * rs + c11 * (inv * acc.x))) * (1.f / 3.f);
    m4.y = (t.y + (c00 * l0.y * rs + c01 * t.y) + (c10 * l1.y * rs + c11 * (inv * acc.y))) * (1.f / 3.f);
    m4.z = (t.z + (c00 * l0.z * rs + c01 * t.z) + (c10 * l1.z * rs + c11 * (inv * acc.z))) * (1.f / 3.f);
    m4.w = (t.w + (c00 * l0.w * rs + c01 * t.w) + (c10 * l1.w * rs + c11 * (inv * acc.w))) * (1.f / 3.f);
    float sq = m4.x * m4.x + m4.y * m4.y + m4.z * m4.z + m4.w * m4.w;
    #pragma unroll
    for (int o = 8; o; o >>= 1) sq += __shfl_xor_sync(0xffffffffu, sq, o);  // 16-lane groups
    float rn = 1.f / fmaxf(sqrtf(sq), 1e-12f);
    return make_float4(t.x + m4.x * rn, t.y + m4.y * rn,
                       t.z + m4.z * rn, t.w + m4.w * rn);
}

// ---------------------------------------------------------------------------
// 7) behavior-0 gather + combine, RESTRICTED to fneed nodes: buf0 -> buf1
// ---------------------------------------------------------------------------
__global__ __launch_bounds__(256) void gathcomb_kernel(const float* __restrict__ ls,
                                                       const float* __restrict__ cw) {
    int node = blockIdx.x * 8 + (threadIdx.x >> 5);
    if (node >= NN) return;
    if (!__ldg(g_fneed + node)) return;            // dead node: buf1 never read
    int lane = threadIdx.x & 31;
    int half = lane >> 4;
    int q    = lane & 15;

    const float* tot_in  = g_total[0];
    float*       tot_out = g_total[1];

    int r0  = __ldg(g_off + node);
    int r1  = __ldg(g_off + node + 1);

    float4 acc = csr_gather(tot_in, g_csrc, g_ns, r0, r1 - r0, lane, half, q);

    float inv = __ldg(g_ns + node);
    float rs  = __ldg(g_rs + node);

    size_t base4 = (size_t)node * DD + q * 4;
    float4 t  = __ldg((const float4*)(tot_in + base4));
    float4 l0 = __ldg((const float4*)(ls + base4));
    float4 l1 = __ldg((const float4*)(ls + (size_t)NN * DD + base4));

    float4 outv = combine_row(t, l0, l1, acc, inv, rs, cw);
    if (half == 0) *(float4*)(tot_out + base4) = outv;
}

// ---------------------------------------------------------------------------
// 8) behavior-1 gather+combine restricted to batch nodes -> g_bemb
// ---------------------------------------------------------------------------
__global__ __launch_bounds__(256) void batch_gath_kernel(const float* __restrict__ ls1,
                                                         const float* __restrict__ cw1,
                                                         const int* __restrict__ bdata) {
    int gw = blockIdx.x * 8 + (threadIdx.x >> 5);   // [0, 3*BATCHSZ)
    if (gw >= 3 * BATCHSZ) return;
    int w = gw / 3, role = gw - w * 3;
    int lane = threadIdx.x & 31;
    int half = lane >> 4;
    int q    = lane & 15;

    const int* row = bdata + (size_t)w * 6 + 3;     // behavior-1 triple
    int node = (role == 0) ? __ldg(row) : NU + __ldg(row + role);

    const float* tot_in = g_total[1];
    const int*   csrc   = g_csrc + (size_t)NE;
    const float* nsb    = g_ns + NN;

    int r0 = __ldg(g_off + (NN + 1) + node);
    int r1 = __ldg(g_off + (NN + 1) + node + 1);

    float4 acc = csr_gather(tot_in, csrc, nsb, r0, r1 - r0, lane, half, q);

    float inv = __ldg(g_ns + NN + node);
    float rs  = __ldg(g_rs + NN + node);

    size_t base4 = (size_t)node * DD + q * 4;
    float4 t  = __ldg((const float4*)(tot_in + base4));
    float4 l0 = __ldg((const float4*)(ls1 + base4));
    float4 l1 = __ldg((const float4*)(ls1 + (size_t)NN * DD + base4));

    float4 outv = combine_row(t, l0, l1, acc, inv, rs, cw1);
    if (half == 0)
        *(float4*)(g_bemb + (size_t)gw * DD + q * 4) = outv;
}

// ---------------------------------------------------------------------------
// 9) BPR loss for both behaviors: b=0 from buf1, b=1 from g_bemb
// ---------------------------------------------------------------------------
__global__ __launch_bounds__(256) void lossall_kernel(const int* __restrict__ bdata) {
    int W = blockIdx.x * 8 + (threadIdx.x >> 5);    // [0, 2*BATCHSZ)
    if (W >= 2 * BATCHSZ) return;
    int b = W >= BATCHSZ;
    int w = W - b * BATCHSZ;
    int lane = threadIdx.x & 31;

    float2 uv, pv, nv;
    if (b == 0) {
        const float* emb = g_total[1];
        const int* r = bdata + (size_t)w * 6;
        int u  = __ldg(r + 0);
        int pi = NU + __ldg(r + 1);
        int ni = NU + __ldg(r + 2);
        uv = *(const float2*)(emb + (size_t)u  * DD + lane * 2);
        pv = *(const float2*)(emb + (size_t)pi * DD + lane * 2);
        nv = *(const float2*)(emb + (size_t)ni * DD + lane * 2);
    } else {
        const float* e = g_bemb + (size_t)w * 3 * DD;
        uv = *(const float2*)(e + lane * 2);
        pv = *(const float2*)(e + DD + lane * 2);
        nv = *(const float2*)(e + 2 * DD + lane * 2);
    }

    float s0 = uv.x * pv.x + uv.y * pv.y;
    float s1 = uv.x * nv.x + uv.y * nv.y;
    #pragma unroll
    for (int o = 16; o; o >>= 1) {
        s0 += __shfl_xor_sync(0xffffffffu, s0, o);
        s1 += __shfl_xor_sync(0xffffffffu, s1, o);
    }
    if (lane == 0) {
        float diff = s0 - s1;
        float sig  = 1.f / (1.f + expf(-diff));
        g_bpr[b * BATCHSZ + w] = -logf(GAMMAF + sig);
    }
}

// ---------------------------------------------------------------------------
// 10) final deterministic reduction -> out[0]
// ---------------------------------------------------------------------------
__global__ __launch_bounds__(1024) void final_kernel(float* __restrict__ out) {
    __shared__ float sh[1024];
    int t = threadIdx.x;

    float a = 0.f;
    for (int i = t; i < 2 * BATCHSZ; i += 1024) a += g_bpr[i];
    float su = 0.f, si = 0.f;
    for (int i = t; i < INIT_BLOCKS; i += 1024) { su += g_squ[i]; si += g_sqi[i]; }

    float res[3] = {a, su, si};
    float red[3];
    #pragma unroll
    for (int k = 0; k < 3; k++) {
        sh[t] = res[k];
        __syncthreads();
        for (int s = 512; s; s >>= 1) {
            if (t < s) sh[t] += sh[t + s];
            __syncthreads();
        }
        red[k] = sh[0];
        __syncthreads();
    }

    if (t == 0) {
        float total_loss = red[0] * (1.f / BATCHSZ);
        float emb_loss   = (sqrtf(red[1]) + sqrtf(red[2])) / (float)NI;
        out[0] = total_loss + 1e-4f * emb_loss;
    }
}

// ---------------------------------------------------------------------------
extern "C" void kernel_launch(void* const* d_in, const int* in_sizes, int n_in,
                              void* d_out, int out_size) {
    const float* ue    = (const float*)d_in[0];
    const float* ie    = (const float*)d_in[1];
    const float* nowd  = (const float*)d_in[2];
    const float* oldd  = (const float*)d_in[3];
    const float* ls    = (const float*)d_in[4];
    const float* dw    = (const float*)d_in[5];
    const float* ow    = (const float*)d_in[6];
    const float* cw    = (const float*)d_in[7];
    const int*   src   = (const int*)d_in[8];
    const int*   dst   = (const int*)d_in[9];
    const int*   bdata = (const int*)d_in[10];
    float*       out   = (float*)d_out;

    init_kernel<<<INIT_BLOCKS, 256>>>((const float4*)ue, (const float4*)ie,
                                      oldd, nowd, dw, ow);
    bmark_kernel<<<(BATCHSZ + 255) / 256, 256>>>(bdata);
    hist_kernel<<<(2 * NE / 4 + 255) / 256, 256>>>((const int4*)dst);
    reduce_kernel<<<2 * SNB, 256>>>();
    scanb_kernel<<<1, 32>>>();
    scanc_kernel<<<2 * SNB, 1024>>>();
    fill_kernel<<<(2 * NE / 4 + 255) / 256, 256>>>((const int4*)src, (const int4*)dst);
    smark_kernel<<<3 * BATCHSZ / 8, 256>>>(bdata);

    // behavior 0: frontier-restricted, buf0 -> buf1
    gathcomb_kernel<<<GB, 256>>>(ls, cw);
    // behavior 1: batch-restricted, buf1 -> g_bemb
    batch_gath_kernel<<<3 * BATCHSZ / 8, 256>>>(ls + (size_t)2 * NN * DD, cw + 4, bdata);
    lossall_kernel<<<2 * BATCHSZ / 8, 256>>>(bdata);

    final_kernel<<<1, 1024>>>(out);
}

// round 17
// speedup vs baseline: 2.3347x; 1.0053x over previous
#include <cuda_runtime.h>
#include <cuda_bf16.h>

#define NU      50001
#define NI      100001
#define NN      150002
#define DD      64
#define NE      2000000
#define BATCHSZ 2048
#define EPSF    1e-9f
#define GAMMAF  1e-10f
#define INIT_BLOCKS 9376   // ceil(NN*DD/4 / 256)
#define NORM_ELEMS  (2 * NN)
#define SCHUNK  4096
#define SNB     37         // ceil(NN / SCHUNK)
#define GB      18751      // ceil(NN / 8)

// ---------------- static scratch ----------------
__device__ __align__(128) float g_buf1[(size_t)NN * DD];     // behavior-0 output, 38.4 MB
__device__ int   g_cnt[2 * NN];
__device__ int   g_off[2 * (NN + 1)];
__device__ int   g_cur[2 * NN];
__device__ int   g_csrc[2 * NE];                             // CSR: src per slot
__device__ float g_ns[2 * NN];                               // 1/(den+eps)
__device__ float g_rs[2 * NN];                               // old_scale/(den+eps)
__device__ float g_bemb[(size_t)3 * BATCHSZ * DD];           // b=1 batch embeddings
__device__ float g_bpr[2 * BATCHSZ];
__device__ float g_squ[INIT_BLOCKS];
__device__ float g_sqi[INIT_BLOCKS];
__device__ int   g_bsum[2 * SNB];
__device__ int   g_bbase[2 * SNB];
__device__ int   g_fb1[NN];                                  // b1 batch-node flag
__device__ int   g_fneed[NN];                                // node needs buf1 value

// ---------------------------------------------------------------------------
// 1) init: per-node norms + flag/counter clear + sumsq partials (NO concat)
// ---------------------------------------------------------------------------
__global__ __launch_bounds__(256) void init_kernel(
    const float4* __restrict__ ue, const float4* __restrict__ ie,
    const float* __restrict__ oldd, const float* __restrict__ nowd,
    const float* __restrict__ dwp, const float* __restrict__ owp)
{
    __shared__ float shu[256], shi[256];
    int i = blockIdx.x * 256 + threadIdx.x;

    if (i < NORM_ELEMS) {
        float dw = __ldg(dwp), ow = __ldg(owp);
        float od = __ldg(oldd + i), nd = __ldg(nowd + i);
        float den = sqrtf(fmaxf(od * dw, 0.f) + nd);
        float inv = 1.f / (den + EPSF);
        g_ns[i] = inv;
        g_rs[i] = sqrtf(fmaxf(od * ow, 0.f)) * inv;
        g_cnt[i] = 0;
    }
    if (i < NN) { g_fb1[i] = 0; g_fneed[i] = 0; }

    const int tot4 = NN * DD / 4;
    const int nu4  = NU * DD / 4;
    float su = 0.f, si = 0.f;
    if (i < tot4) {
        if (i < nu4) { float4 v = __ldg(ue + i);        su = v.x*v.x + v.y*v.y + v.z*v.z + v.w*v.w; }
        else         { float4 v = __ldg(ie + i - nu4);  si = v.x*v.x + v.y*v.y + v.z*v.z + v.w*v.w; }
    }
    shu[threadIdx.x] = su; shi[threadIdx.x] = si;
    __syncthreads();
    for (int s = 128; s; s >>= 1) {
        if (threadIdx.x < s) {
            shu[threadIdx.x] += shu[threadIdx.x + s];
            shi[threadIdx.x] += shi[threadIdx.x + s];
        }
        __syncthreads();
    }
    if (threadIdx.x == 0) { g_squ[blockIdx.x] = shu[0]; g_sqi[blockIdx.x] = shi[0]; }
}

// ---------------------------------------------------------------------------
// 2) mark batch nodes: fb1 for b1 triples, fneed for both triples
// ---------------------------------------------------------------------------
__global__ __launch_bounds__(256) void bmark_kernel(const int* __restrict__ bdata) {
    int w = blockIdx.x * 256 + threadIdx.x;
    if (w >= BATCHSZ) return;
    const int* r = bdata + (size_t)w * 6;
    int u0 = __ldg(r + 0), p0 = NU + __ldg(r + 1), n0 = NU + __ldg(r + 2);
    int u1 = __ldg(r + 3), p1 = NU + __ldg(r + 4), n1 = NU + __ldg(r + 5);
    g_fneed[u0] = 1; g_fneed[p0] = 1; g_fneed[n0] = 1;
    g_fneed[u1] = 1; g_fneed[p1] = 1; g_fneed[n1] = 1;
    g_fb1[u1] = 1;   g_fb1[p1] = 1;   g_fb1[n1] = 1;
}

// ---------------------------------------------------------------------------
// 3) b1 histogram (filtered by fb1[dst]) + frontier mark fneed[src]
// ---------------------------------------------------------------------------
__global__ __launch_bounds__(256) void histb1_kernel(const int4* __restrict__ dst4,
                                                     const int4* __restrict__ src4) {
    int i = blockIdx.x * 256 + threadIdx.x;      // [0, NE/4)
    if (i >= NE / 4) return;
    int4 d = __ldg(dst4 + i);
    int4 s = __ldg(src4 + i);
    int* c = g_cnt + NN;
    if (__ldg(g_fb1 + d.x)) { atomicAdd(c + d.x, 1); g_fneed[s.x] = 1; }
    if (__ldg(g_fb1 + d.y)) { atomicAdd(c + d.y, 1); g_fneed[s.y] = 1; }
    if (__ldg(g_fb1 + d.z)) { atomicAdd(c + d.z, 1); g_fneed[s.z] = 1; }
    if (__ldg(g_fb1 + d.w)) { atomicAdd(c + d.w, 1); g_fneed[s.w] = 1; }
}

// ---------------------------------------------------------------------------
// 4) b0 histogram, filtered by fneed[dst] (complete after histb1)
// ---------------------------------------------------------------------------
__global__ __launch_bounds__(256) void histb0_kernel(const int4* __restrict__ dst4) {
    int i = blockIdx.x * 256 + threadIdx.x;      // [0, NE/4)
    if (i >= NE / 4) return;
    int4 d = __ldg(dst4 + i);
    int* c = g_cnt;
    if (__ldg(g_fneed + d.x)) atomicAdd(c + d.x, 1);
    if (__ldg(g_fneed + d.y)) atomicAdd(c + d.y, 1);
    if (__ldg(g_fneed + d.z)) atomicAdd(c + d.z, 1);
    if (__ldg(g_fneed + d.w)) atomicAdd(c + d.w, 1);
}

// ---------------------------------------------------------------------------
// 5a) chunk sums
// ---------------------------------------------------------------------------
__global__ __launch_bounds__(256) void reduce_kernel() {
    __shared__ int sh[256];
    int blk = blockIdx.x;              // [0, 2*SNB)
    int b   = blk >= SNB;
    int c   = blk - b * SNB;
    const int* cnt = g_cnt + b * NN;
    int s = 0;
    int base = c * SCHUNK;
    #pragma unroll
    for (int k = 0; k < SCHUNK / 256; k++) {
        int i = base + k * 256 + threadIdx.x;
        if (i < NN) s += cnt[i];
    }
    sh[threadIdx.x] = s;
    __syncthreads();
    for (int st = 128; st; st >>= 1) {
        if (threadIdx.x < st) sh[threadIdx.x] += sh[threadIdx.x + st];
        __syncthreads();
    }
    if (threadIdx.x == 0) g_bsum[blk] = sh[0];
}

// ---------------------------------------------------------------------------
// 5b) scan the SNB partials per behavior
// ---------------------------------------------------------------------------
__global__ void scanb_kernel() {
    int b = threadIdx.x;
    if (b < 2) {
        int run = 0;
        for (int i = 0; i < SNB; i++) {
            g_bbase[b * SNB + i] = run;
            run += g_bsum[b * SNB + i];
        }
        g_off[b * (NN + 1) + NN] = run;
    }
}

// ---------------------------------------------------------------------------
// 5c) intra-chunk exclusive scan + base -> off, cur
// ---------------------------------------------------------------------------
__global__ __launch_bounds__(1024) void scanc_kernel() {
    int blk = blockIdx.x;              // [0, 2*SNB)
    int b   = blk >= SNB;
    int c   = blk - b * SNB;
    int tid = threadIdx.x, lane = tid & 31, wid = tid >> 5;
    __shared__ int wsum[32];

    const int* cnt = g_cnt + b * NN;
    int* off = g_off + b * (NN + 1);
    int* cur = g_cur + b * NN;

    int i0 = c * SCHUNK + tid * 4;
    int v0 = (i0 + 0 < NN) ? cnt[i0 + 0] : 0;
    int v1 = (i0 + 1 < NN) ? cnt[i0 + 1] : 0;
    int v2 = (i0 + 2 < NN) ? cnt[i0 + 2] : 0;
    int v3 = (i0 + 3 < NN) ? cnt[i0 + 3] : 0;
    int ts = v0 + v1 + v2 + v3;
    int x = ts;
    #pragma unroll
    for (int o = 1; o < 32; o <<= 1) { int y = __shfl_up_sync(~0u, x, o); if (lane >= o) x += y; }
    if (lane == 31) wsum[wid] = x;
    __syncthreads();
    if (wid == 0) {
        int w = wsum[lane];
        #pragma unroll
        for (int o = 1; o < 32; o <<= 1) { int y = __shfl_up_sync(~0u, w, o); if (lane >= o) w += y; }
        wsum[lane] = w;
    }
    __syncthreads();
    int excl = g_bbase[blk] + (x - ts) + (wid ? wsum[wid - 1] : 0);
    if (i0 + 0 < NN) { off[i0 + 0] = excl; cur[i0 + 0] = excl; } excl += v0;
    if (i0 + 1 < NN) { off[i0 + 1] = excl; cur[i0 + 1] = excl; } excl += v1;
    if (i0 + 2 < NN) { off[i0 + 2] = excl; cur[i0 + 2] = excl; } excl += v2;
    if (i0 + 3 < NN) { off[i0 + 3] = excl; cur[i0 + 3] = excl; }
}

// ---------------------------------------------------------------------------
// 6) CSR fill; b0 filtered by fneed[dst], b1 filtered by fb1[dst]
// ---------------------------------------------------------------------------
__global__ __launch_bounds__(256) void fill_kernel(const int4* __restrict__ src4,
                                                   const int4* __restrict__ dst4) {
    int i = blockIdx.x * 256 + threadIdx.x;      // [0, 2*NE/4)
    if (i >= 2 * NE / 4) return;
    int4 d = __ldg(dst4 + i);
    int4 s = __ldg(src4 + i);
    if (i < NE / 4) {
        int* cur = g_cur;
        int* csrc = g_csrc;
        if (__ldg(g_fneed + d.x)) csrc[atomicAdd(cur + d.x, 1)] = s.x;
        if (__ldg(g_fneed + d.y)) csrc[atomicAdd(cur + d.y, 1)] = s.y;
        if (__ldg(g_fneed + d.z)) csrc[atomicAdd(cur + d.z, 1)] = s.z;
        if (__ldg(g_fneed + d.w)) csrc[atomicAdd(cur + d.w, 1)] = s.w;
    } else {
        int* cur = g_cur + NN;
        int* csrc = g_csrc + (size_t)NE;
        if (__ldg(g_fb1 + d.x)) csrc[atomicAdd(cur + d.x, 1)] = s.x;
        if (__ldg(g_fb1 + d.y)) csrc[atomicAdd(cur + d.y, 1)] = s.y;
        if (__ldg(g_fb1 + d.z)) csrc[atomicAdd(cur + d.z, 1)] = s.z;
        if (__ldg(g_fb1 + d.w)) csrc[atomicAdd(cur + d.w, 1)] = s.w;
    }
}

// ---------------------------------------------------------------------------
// device helpers
// ---------------------------------------------------------------------------
__device__ __forceinline__ const float* emb0_row(const float* __restrict__ ue,
                                                 const float* __restrict__ ie, int node) {
    return (node < NU) ? (ue + (size_t)node * DD) : (ie + (size_t)(node - NU) * DD);
}

// gather from split input embeddings (behavior 0)
__device__ __forceinline__ float4 csr_gather0(const float* __restrict__ ue,
                                              const float* __restrict__ ie,
                                              const int* __restrict__ csrc,
                                              const float* __restrict__ nsb,
                                              int r0, int cnt,
                                              int lane, int half, int q) {
    float4 acc = make_float4(0.f, 0.f, 0.f, 0.f);
    for (int base = 0; base < cnt; base += 32) {
        int mm = min(32, cnt - base);
        int myidx = 0; float myns = 0.f;
        if (base + lane < cnt) {
            myidx = __ldg(csrc + r0 + base + lane);
            myns  = __ldg(nsb + myidx);
        }
        int kend = mm & ~1;
        #pragma unroll 4
        for (int k = 0; k < kend; k += 2) {
            int   s = __shfl_sync(0xffffffffu, myidx, k + half);
            float w = __shfl_sync(0xffffffffu, myns,  k + half);
            float4 v = __ldg((const float4*)(emb0_row(ue, ie, s) + q * 4));
            acc.x = fmaf(w, v.x, acc.x);
            acc.y = fmaf(w, v.y, acc.y);
            acc.z = fmaf(w, v.z, acc.z);
            acc.w = fmaf(w, v.w, acc.w);
        }
        if (mm & 1) {
            int   s = __shfl_sync(0xffffffffu, myidx, kend);
            float w = __shfl_sync(0xffffffffu, myns,  kend);
            if (half == 0) {
                float4 v = __ldg((const float4*)(emb0_row(ue, ie, s) + q * 4));
                acc.x = fmaf(w, v.x, acc.x);
                acc.y = fmaf(w, v.y, acc.y);
                acc.z = fmaf(w, v.z, acc.z);
                acc.w = fmaf(w, v.w, acc.w);
            }
        }
    }
    acc.x += __shfl_xor_sync(0xffffffffu, acc.x, 16);
    acc.y += __shfl_xor_sync(0xffffffffu, acc.y, 16);
    acc.z += __shfl_xor_sync(0xffffffffu, acc.z, 16);
    acc.w += __shfl_xor_sync(0xffffffffu, acc.w, 16);
    return acc;
}

// gather from a single contiguous buffer (behavior 1, from g_buf1)
__device__ __forceinline__ float4 csr_gather(const float* __restrict__ tot_in,
                                             const int* __restrict__ csrc,
                                             const float* __restrict__ nsb,
                                             int r0, int cnt,
                                             int lane, int half, int q) {
    float4 acc = make_float4(0.f, 0.f, 0.f, 0.f);
    for (int base = 0; base < cnt; base += 32) {
        int mm = min(32, cnt - base);
        int myidx = 0; float myns = 0.f;
        if (base + lane < cnt) {
            myidx = __ldg(csrc + r0 + base + lane);
            myns  = __ldg(nsb + myidx);
        }
        int kend = mm & ~1;
        #pragma unroll 4
        for (int k = 0; k < kend; k += 2) {
            int   s = __shfl_sync(0xffffffffu, myidx, k + half);
            float w = __shfl_sync(0xffffffffu, myns,  k + half);
            float4 v = __ldg((const float4*)(tot_in + (size_t)s * DD + q * 4));
            acc.x = fmaf(w, v.x, acc.x);
            acc.y = fmaf(w, v.y, acc.y);
            acc.z = fmaf(w, v.z, acc.z);
            acc.w = fmaf(w, v.w, acc.w);
        }
        if (mm & 1) {
            int   s = __shfl_sync(0xffffffffu, myidx, kend);
            float w = __shfl_sync(0xffffffffu, myns,  kend);
            if (half == 0) {
                float4 v = __ldg((const float4*)(tot_in + (size_t)s * DD + q * 4));
                acc.x = fmaf(w, v.x, acc.x);
                acc.y = fmaf(w, v.y, acc.y);
                acc.z = fmaf(w, v.z, acc.z);
                acc.w = fmaf(w, v.w, acc.w);
            }
        }
    }
    acc.x += __shfl_xor_sync(0xffffffffu, acc.x, 16);
    acc.y += __shfl_xor_sync(0xffffffffu, acc.y, 16);
    acc.z += __shfl_xor_sync(0xffffffffu, acc.z, 16);
    acc.w += __shfl_xor_sync(0xffffffffu, acc.w, 16);
    return acc;
}

__device__ __forceinline__ float4 combine_row(float4 t, float4 l0, float4 l1, float4 acc,
                                              float inv, float rs,
                                              const float* __restrict__ cw) {
    float c00 = __ldg(cw + 0), c01 = __ldg(cw + 1);
    float c10 = __ldg(cw + 2), c11 = __ldg(cw + 3);
    float4 m4;
    m4.x = (t.x + (c00 * l0.x * rs + c01 * t.x) + (c10 * l1.x * rs + c11 * (inv * acc.x))) * (1.f / 3.f);
    m4.y = (t.y + (c00 * l0.y * rs + c01 * t.y) + (c10 * l1.y * rs + c11 * (inv * acc.y))) * (1.f / 3.f);
    m4.z = (t.z + (c00 * l0.z * rs + c01 * t.z) + (c10 * l1.z * rs + c11 * (inv * acc.z))) * (1.f / 3.f);
    m4.w = (t.w + (c00 * l0.w * rs + c01 * t.w) + (c10 * l1.w * rs + c11 * (inv * acc.w))) * (1.f / 3.f);
    float sq = m4.x * m4.x + m4.y * m4.y + m4.z * m4.z + m4.w * m4.w;
    #pragma unroll
    for (int o = 8; o; o >>= 1) sq += __shfl_xor_sync(0xffffffffu, sq, o);  // 16-lane groups
    float rn = 1.f / fmaxf(sqrtf(sq), 1e-12f);
    return make_float4(t.x + m4.x * rn, t.y + m4.y * rn,
                       t.z + m4.z * rn, t.w + m4.w * rn);
}

// ---------------------------------------------------------------------------
// 7) behavior-0 gather + combine, fneed nodes only: (ue,ie) -> buf1
// ---------------------------------------------------------------------------
__global__ __launch_bounds__(256) void gathcomb_kernel(const float* __restrict__ ue,
                                                       const float* __restrict__ ie,
                                                       const float* __restrict__ ls,
                                                       const float* __restrict__ cw) {
    int node = blockIdx.x * 8 + (threadIdx.x >> 5);
    if (node >= NN) return;
    if (!__ldg(g_fneed + node)) return;
    int lane = threadIdx.x & 31;
    int half = lane >> 4;
    int q    = lane & 15;

    int r0  = __ldg(g_off + node);
    int r1  = __ldg(g_off + node + 1);

    float4 acc = csr_gather0(ue, ie, g_csrc, g_ns, r0, r1 - r0, lane, half, q);

    float inv = __ldg(g_ns + node);
    float rs  = __ldg(g_rs + node);

    size_t base4 = (size_t)node * DD + q * 4;
    float4 t  = __ldg((const float4*)(emb0_row(ue, ie, node) + q * 4));
    float4 l0 = __ldg((const float4*)(ls + base4));
    float4 l1 = __ldg((const float4*)(ls + (size_t)NN * DD + base4));

    float4 outv = combine_row(t, l0, l1, acc, inv, rs, cw);
    if (half == 0) *(float4*)(g_buf1 + base4) = outv;
}

// ---------------------------------------------------------------------------
// 8) behavior-1 gather+combine restricted to batch nodes -> g_bemb
// ---------------------------------------------------------------------------
__global__ __launch_bounds__(256) void batch_gath_kernel(const float* __restrict__ ls1,
                                                         const float* __restrict__ cw1,
                                                         const int* __restrict__ bdata) {
    int gw = blockIdx.x * 8 + (threadIdx.x >> 5);   // [0, 3*BATCHSZ)
    if (gw >= 3 * BATCHSZ) return;
    int w = gw / 3, role = gw - w * 3;
    int lane = threadIdx.x & 31;
    int half = lane >> 4;
    int q    = lane & 15;

    const int* row = bdata + (size_t)w * 6 + 3;     // behavior-1 triple
    int node = (role == 0) ? __ldg(row) : NU + __ldg(row + role);

    const int*   csrc = g_csrc + (size_t)NE;
    const float* nsb  = g_ns + NN;

    int r0 = __ldg(g_off + (NN + 1) + node);
    int r1 = __ldg(g_off + (NN + 1) + node + 1);

    float4 acc = csr_gather(g_buf1, csrc, nsb, r0, r1 - r0, lane, half, q);

    float inv = __ldg(g_ns + NN + node);
    float rs  = __ldg(g_rs + NN + node);

    size_t base4 = (size_t)node * DD + q * 4;
    float4 t  = __ldg((const float4*)(g_buf1 + base4));
    float4 l0 = __ldg((const float4*)(ls1 + base4));
    float4 l1 = __ldg((const float4*)(ls1 + (size_t)NN * DD + base4));

    float4 outv = combine_row(t, l0, l1, acc, inv, rs, cw1);
    if (half == 0)
        *(float4*)(g_bemb + (size_t)gw * DD + q * 4) = outv;
}

// ---------------------------------------------------------------------------
// 9) BPR loss for both behaviors: b=0 from buf1, b=1 from g_bemb
// ---------------------------------------------------------------------------
__global__ __launch_bounds__(256) void lossall_kernel(const int* __restrict__ bdata) {
    int W = blockIdx.x * 8 + (threadIdx.x >> 5);    // [0, 2*BATCHSZ)
    if (W >= 2 * BATCHSZ) return;
    int b = W >= BATCHSZ;
    int w = W - b * BATCHSZ;
    int lane = threadIdx.x & 31;

    float2 uv, pv, nv;
    if (b == 0) {
        const int* r = bdata + (size_t)w * 6;
        int u  = __ldg(r + 0);
        int pi = NU + __ldg(r + 1);
        int ni = NU + __ldg(r + 2);
        uv = *(const float2*)(g_buf1 + (size_t)u  * DD + lane * 2);
        pv = *(const float2*)(g_buf1 + (size_t)pi * DD + lane * 2);
        nv = *(const float2*)(g_buf1 + (size_t)ni * DD + lane * 2);
    } else {
        const float* e = g_bemb + (size_t)w * 3 * DD;
        uv = *(const float2*)(e + lane * 2);
        pv = *(const float2*)(e + DD + lane * 2);
        nv = *(const float2*)(e + 2 * DD + lane * 2);
    }

    float s0 = uv.x * pv.x + uv.y * pv.y;
    float s1 = uv.x * nv.x + uv.y * nv.y;
    #pragma unroll
    for (int o = 16; o; o >>= 1) {
        s0 += __shfl_xor_sync(0xffffffffu, s0, o);
        s1 += __shfl_xor_sync(0xffffffffu, s1, o);
    }
    if (lane == 0) {
        float diff = s0 - s1;
        float sig  = 1.f / (1.f + expf(-diff));
        g_bpr[b * BATCHSZ + w] = -logf(GAMMAF + sig);
    }
}

// ---------------------------------------------------------------------------
// 10) final deterministic reduction -> out[0]
// ---------------------------------------------------------------------------
__global__ __launch_bounds__(1024) void final_kernel(float* __restrict__ out) {
    __shared__ float sh[1024];
    int t = threadIdx.x;

    float a = 0.f;
    for (int i = t; i < 2 * BATCHSZ; i += 1024) a += g_bpr[i];
    float su = 0.f, si = 0.f;
    for (int i = t; i < INIT_BLOCKS; i += 1024) { su += g_squ[i]; si += g_sqi[i]; }

    float res[3] = {a, su, si};
    float red[3];
    #pragma unroll
    for (int k = 0; k < 3; k++) {
        sh[t] = res[k];
        __syncthreads();
        for (int s = 512; s; s >>= 1) {
            if (t < s) sh[t] += sh[t + s];
            __syncthreads();
        }
        red[k] = sh[0];
        __syncthreads();
    }

    if (t == 0) {
        float total_loss = red[0] * (1.f / BATCHSZ);
        float emb_loss   = (sqrtf(red[1]) + sqrtf(red[2])) / (float)NI;
        out[0] = total_loss + 1e-4f * emb_loss;
    }
}

// ---------------------------------------------------------------------------
extern "C" void kernel_launch(void* const* d_in, const int* in_sizes, int n_in,
                              void* d_out, int out_size) {
    const float* ue    = (const float*)d_in[0];
    const float* ie    = (const float*)d_in[1];
    const float* nowd  = (const float*)d_in[2];
    const float* oldd  = (const float*)d_in[3];
    const float* ls    = (const float*)d_in[4];
    const float* dw    = (const float*)d_in[5];
    const float* ow    = (const float*)d_in[6];
    const float* cw    = (const float*)d_in[7];
    const int*   src   = (const int*)d_in[8];
    const int*   dst   = (const int*)d_in[9];
    const int*   bdata = (const int*)d_in[10];
    float*       out   = (float*)d_out;

    init_kernel<<<INIT_BLOCKS, 256>>>((const float4*)ue, (const float4*)ie,
                                      oldd, nowd, dw, ow);
    bmark_kernel<<<(BATCHSZ + 255) / 256, 256>>>(bdata);
    // b1 first: defines fneed (sources of b1 batch rows)
    histb1_kernel<<<(NE / 4 + 255) / 256, 256>>>((const int4*)(dst + (size_t)NE),
                                                 (const int4*)(src + (size_t)NE));
    histb0_kernel<<<(NE / 4 + 255) / 256, 256>>>((const int4*)dst);
    reduce_kernel<<<2 * SNB, 256>>>();
    scanb_kernel<<<1, 32>>>();
    scanc_kernel<<<2 * SNB, 1024>>>();
    fill_kernel<<<(2 * NE / 4 + 255) / 256, 256>>>((const int4*)src, (const int4*)dst);

    // behavior 0: frontier-restricted, (ue,ie) -> buf1
    gathcomb_kernel<<<GB, 256>>>(ue, ie, ls, cw);
    // behavior 1: batch-restricted, buf1 -> g_bemb
    batch_gath_kernel<<<3 * BATCHSZ / 8, 256>>>(ls + (size_t)2 * NN * DD, cw + 4, bdata);
    lossall_kernel<<<2 * BATCHSZ / 8, 256>>>(bdata);

    final_kernel<<<1, 1024>>>(out);
}